// round 1
// baseline (speedup 1.0000x reference)
#include <cuda_runtime.h>

#define NB 16
#define LA 1024
#define LT 512
#define DD 256

// ---------------- scratch (no allocation allowed) ----------------
__device__ float g_bufA0[NB*LA*DD];
__device__ float g_bufA1[NB*LA*DD];
__device__ float g_bufT0[NB*LT*DD];
__device__ float g_bufT1[NB*LT*DD];
__device__ float g_norm[NB*LA + NB*LT];   // art norms then tpl norms
__device__ float g_rowmax[NB*LA];

// ---------------- f32x2 helpers ----------------
__device__ __forceinline__ unsigned long long bcast2(float a) {
    unsigned long long r; unsigned int u = __float_as_uint(a);
    asm("mov.b64 %0, {%1,%1};" : "=l"(r) : "r"(u));
    return r;
}
__device__ __forceinline__ void ffma2(unsigned long long &acc,
                                      unsigned long long a, unsigned long long b) {
    asm("fma.rn.f32x2 %0, %1, %2, %0;" : "+l"(acc) : "l"(a), "l"(b));
}
__device__ __forceinline__ float2 unpk(unsigned long long v) {
    unsigned int lo, hi;
    asm("mov.b64 {%0,%1}, %2;" : "=r"(lo), "=r"(hi) : "l"(v));
    return make_float2(__uint_as_float(lo), __uint_as_float(hi));
}

// ---------------- embedding gather ----------------
__global__ void embed_kernel(const int* __restrict__ aw, const int* __restrict__ tw,
                             const float* __restrict__ emb)
{
    int row = blockIdx.x;          // 0 .. NB*LA + NB*LT - 1
    int t   = threadIdx.x;         // 64 threads * float4 = 256 floats
    const float4* src; float4* dst;
    if (row < NB*LA) {
        src = (const float4*)(emb + (size_t)aw[row] * DD);
        dst = (float4*)(g_bufA0 + (size_t)row * DD);
    } else {
        int r = row - NB*LA;
        src = (const float4*)(emb + (size_t)tw[r] * DD);
        dst = (float4*)(g_bufT0 + (size_t)r * DD);
    }
    dst[t] = src[t];
}

// ---------------- residual dilated conv + GLU (implicit GEMM) ----------------
// y[l,o] = sum_{k,i} x[l+(k-1)*dil, i] * w[k,i,o] + b[o];  out = x + y[:256]*sigmoid(y[256:])
// Block: 64 positions x 128 a-channels (=> 256 y-channels). 256 threads.
// Thread: 4 positions x (8 a + 8 g) channels, f32x2-packed accumulators.
__global__ __launch_bounds__(256, 2)
void conv_glu_kernel(int seq, int par, const float* __restrict__ w,
                     const float* __restrict__ bias, int dil, int L)
{
    const float* xin; float* xout;
    if (seq == 0) { xin = par ? g_bufA1 : g_bufA0; xout = par ? g_bufA0 : g_bufA1; }
    else          { xin = par ? g_bufT1 : g_bufT0; xout = par ? g_bufT0 : g_bufT1; }

    const int b  = blockIdx.z;
    const int l0 = blockIdx.x * 64;
    const int cb = blockIdx.y * 128;      // a-channel base (0 or 128)

    const float* xb  = xin  + (size_t)b * L * DD;
    float*       xob = xout + (size_t)b * L * DD;

    __shared__ float As[64*33];           // [m][j], stride 33
    __shared__ float Bs[32*256];          // [j][y]: y<128 -> a-chan cb+y, y>=128 -> g-chan 256+cb+(y-128)

    const int tid = threadIdx.x;
    const int pg  = tid & 15;             // position group -> m0 = pg*4
    const int cg  = tid >> 4;             // channel group  -> a-chans cb + cg*8 .. +7
    const int m0  = pg * 4;
    const int jl  = tid & 31, mb = tid >> 5;

    unsigned long long accA[4][4], accG[4][4];
#pragma unroll
    for (int i = 0; i < 4; i++)
#pragma unroll
        for (int p = 0; p < 4; p++) { accA[i][p] = 0ull; accG[i][p] = 0ull; }

    for (int k = 0; k < 3; ++k) {
        const int lbase = l0 + (k - 1) * dil;
        for (int j0 = 0; j0 < DD; j0 += 32) {
            __syncthreads();
            // A tile: 64 positions x 32 features (zero-padded outside [0,L))
#pragma unroll
            for (int it = 0; it < 8; ++it) {
                int m = mb + it * 8;
                int l = lbase + m;
                float v = 0.0f;
                if (l >= 0 && l < L) v = xb[(size_t)l * DD + j0 + jl];
                As[m * 33 + jl] = v;
            }
            // B tile: 32 x 256 (a-half and g-half of the weight matrix)
            const float* wk = w + ((size_t)k * DD + j0) * 512;
#pragma unroll
            for (int it = 0; it < 8; ++it) {
                int idx = tid + it * 256;          // float4 index, 0..2047
                int j   = idx >> 6;                // 0..31
                int y   = (idx & 63) * 4;          // 0..252
                int col = cb + y + ((y >= 128) ? 128 : 0);
                float4 v = *(const float4*)(wk + (size_t)j * 512 + col);
                *(float4*)(&Bs[j * 256 + y]) = v;
            }
            __syncthreads();

#pragma unroll 8
            for (int j = 0; j < 32; ++j) {
                unsigned long long ap[4];
#pragma unroll
                for (int i = 0; i < 4; i++) ap[i] = bcast2(As[(m0 + i) * 33 + j]);
                const float* brow = &Bs[j * 256 + cg * 8];
                ulonglong2 bA0 = *(const ulonglong2*)(brow);
                ulonglong2 bA1 = *(const ulonglong2*)(brow + 4);
                ulonglong2 bG0 = *(const ulonglong2*)(brow + 128);
                ulonglong2 bG1 = *(const ulonglong2*)(brow + 132);
#pragma unroll
                for (int i = 0; i < 4; i++) {
                    ffma2(accA[i][0], ap[i], bA0.x);
                    ffma2(accA[i][1], ap[i], bA0.y);
                    ffma2(accA[i][2], ap[i], bA1.x);
                    ffma2(accA[i][3], ap[i], bA1.y);
                    ffma2(accG[i][0], ap[i], bG0.x);
                    ffma2(accG[i][1], ap[i], bG0.y);
                    ffma2(accG[i][2], ap[i], bG1.x);
                    ffma2(accG[i][3], ap[i], bG1.y);
                }
            }
        }
    }

    // epilogue: bias + GLU + residual, fused store
    const int c = cb + cg * 8;
#pragma unroll
    for (int i = 0; i < 4; i++) {
        int l = l0 + m0 + i;
        float o[8];
#pragma unroll
        for (int p = 0; p < 4; p++) {
            float2 a = unpk(accA[i][p]);
            float2 g = unpk(accG[i][p]);
            a.x += bias[c + 2*p];         a.y += bias[c + 2*p + 1];
            g.x += bias[256 + c + 2*p];   g.y += bias[256 + c + 2*p + 1];
            o[2*p]     = a.x / (1.0f + __expf(-g.x));
            o[2*p + 1] = a.y / (1.0f + __expf(-g.y));
        }
        const float4* xr = (const float4*)(xb + (size_t)l * DD + c);
        float4 r0 = xr[0], r1 = xr[1];
        float4* xw = (float4*)(xob + (size_t)l * DD + c);
        xw[0] = make_float4(r0.x + o[0], r0.y + o[1], r0.z + o[2], r0.w + o[3]);
        xw[1] = make_float4(r1.x + o[4], r1.y + o[5], r1.z + o[6], r1.w + o[7]);
    }
}

// ---------------- squared norms ----------------
__global__ void norms_kernel()
{
    int gwarp = (blockIdx.x * blockDim.x + threadIdx.x) >> 5;
    int lane  = threadIdx.x & 31;
    const int total = NB*LA + NB*LT;
    if (gwarp >= total) return;
    const float* row = (gwarp < NB*LA) ? (g_bufA0 + (size_t)gwarp * DD)
                                       : (g_bufT0 + (size_t)(gwarp - NB*LA) * DD);
    const float4* r4 = (const float4*)row;
    float s = 0.f;
#pragma unroll
    for (int i = 0; i < 2; ++i) {
        float4 v = r4[lane + i * 32];
        s += v.x*v.x + v.y*v.y + v.z*v.z + v.w*v.w;
    }
#pragma unroll
    for (int off = 16; off > 0; off >>= 1) s += __shfl_xor_sync(0xffffffffu, s, off);
    if (lane == 0) g_norm[gwarp] = s;
}

// ---------------- pairwise distance + row-max (fused, never materializes S) ----------------
__global__ __launch_bounds__(256)
void distance_rowmax_kernel(const float* __restrict__ am, const float* __restrict__ tm)
{
    const int b  = blockIdx.y;
    const int a0 = blockIdx.x * 64;
    const float* art = g_bufA0 + (size_t)b * LA * DD;
    const float* tpl = g_bufT0 + (size_t)b * LT * DD;
    const float* a2  = g_norm + b * LA;
    const float* t2  = g_norm + NB*LA + b * LT;

    __shared__ float Asx[64*33];
    __shared__ float Tsx[64*33];
    __shared__ float red[64*17];

    const int tid = threadIdx.x;
    const int pg  = tid & 15;     // a group
    const int tg  = tid >> 4;     // t group
    const int jl  = tid & 31, mb = tid >> 5;

    float rmax[4] = {0.f, 0.f, 0.f, 0.f};

    for (int tt = 0; tt < LT; tt += 64) {
        float acc[4][4];
#pragma unroll
        for (int i = 0; i < 4; i++)
#pragma unroll
            for (int q = 0; q < 4; q++) acc[i][q] = 0.f;

        for (int d0 = 0; d0 < DD; d0 += 32) {
            __syncthreads();
#pragma unroll
            for (int it = 0; it < 8; ++it) {
                int m = mb + it * 8;
                Asx[m * 33 + jl] = art[(size_t)(a0 + m) * DD + d0 + jl];
                Tsx[m * 33 + jl] = tpl[(size_t)(tt + m) * DD + d0 + jl];
            }
            __syncthreads();
#pragma unroll 8
            for (int j = 0; j < 32; ++j) {
                float av[4], tv[4];
#pragma unroll
                for (int i = 0; i < 4; i++) av[i] = Asx[(pg*4 + i) * 33 + j];
#pragma unroll
                for (int q = 0; q < 4; q++) tv[q] = Tsx[(tg*4 + q) * 33 + j];
#pragma unroll
                for (int i = 0; i < 4; i++)
#pragma unroll
                    for (int q = 0; q < 4; q++) acc[i][q] += av[i] * tv[q];
            }
        }
#pragma unroll
        for (int i = 0; i < 4; i++) {
            int a = a0 + pg*4 + i;
            float an = a2[a];
#pragma unroll
            for (int q = 0; q < 4; q++) {
                int t = tt + tg*4 + q;
                float dist = fmaxf(an + t2[t] - 2.0f * acc[i][q], 0.0f);
                float val  = __expf(-dist) * tm[b * LT + t];
                rmax[i] = fmaxf(rmax[i], val);
            }
        }
    }
    __syncthreads();
#pragma unroll
    for (int i = 0; i < 4; i++) red[(pg*4 + i) * 17 + tg] = rmax[i];
    __syncthreads();
    if (tid < 64) {
        float m = 0.f;
#pragma unroll
        for (int q = 0; q < 16; q++) m = fmaxf(m, red[tid * 17 + q]);
        g_rowmax[b * LA + a0 + tid] = m * am[b * LA + a0 + tid];
    }
}

// ---------------- top-10 + tiny MLP ----------------
__global__ void topk_mlp_kernel(const float* __restrict__ ff1w, const float* __restrict__ ff1b,
                                const float* __restrict__ ff2w, const float* __restrict__ ff2b,
                                float* __restrict__ out)
{
    const int b = blockIdx.x;
    __shared__ float vals[1024];
    __shared__ float rv[256];
    __shared__ int   ri[256];
    __shared__ float top[10];
    __shared__ float hbuf[10];
    const int tid = threadIdx.x;

    for (int i = tid; i < 1024; i += 256) vals[i] = g_rowmax[b * LA + i];
    __syncthreads();

    for (int it = 0; it < 10; ++it) {
        float best = -1e30f; int bi = 0;
        for (int i = tid; i < 1024; i += 256) {
            float v = vals[i];
            if (v > best) { best = v; bi = i; }
        }
        rv[tid] = best; ri[tid] = bi;
        __syncthreads();
        for (int s = 128; s > 0; s >>= 1) {
            if (tid < s) {
                float ov = rv[tid + s]; int oi = ri[tid + s];
                if (ov > rv[tid] || (ov == rv[tid] && oi < ri[tid])) { rv[tid] = ov; ri[tid] = oi; }
            }
            __syncthreads();
        }
        if (tid == 0) { top[it] = rv[0]; vals[ri[0]] = -1e30f; }
        __syncthreads();
    }

    if (tid < 10) {
        float h = ff1b[tid];
#pragma unroll
        for (int i = 0; i < 10; i++) h += top[i] * ff1w[i * 10 + tid];
        hbuf[tid] = fmaxf(h, 0.f);
    }
    __syncthreads();
    if (tid == 0) {
        float o = ff2b[0];
#pragma unroll
        for (int i = 0; i < 10; i++) o += hbuf[i] * ff2w[i];
        out[b] = o;
    }
}

// ---------------- launch ----------------
extern "C" void kernel_launch(void* const* d_in, const int* in_sizes, int n_in,
                              void* d_out, int out_size)
{
    const int*   aw    = (const int*)  d_in[0];
    const int*   tw    = (const int*)  d_in[2];
    const float* am    = (const float*)d_in[4];
    const float* tm    = (const float*)d_in[5];
    const float* emb   = (const float*)d_in[6];
    const float* exp_w = (const float*)d_in[7];
    const float* exp_b = (const float*)d_in[8];
    const float* ref_w = (const float*)d_in[9];
    const float* ref_b = (const float*)d_in[10];
    const float* ff1w  = (const float*)d_in[11];
    const float* ff1b  = (const float*)d_in[12];
    const float* ff2w  = (const float*)d_in[13];
    const float* ff2b  = (const float*)d_in[14];
    float* out = (float*)d_out;

    embed_kernel<<<NB*LA + NB*LT, 64>>>(aw, tw, emb);

    const int dils[10] = {1, 2, 4, 8, 16, 32, 32, 1, 1, 1};
    for (int layer = 0; layer < 10; ++layer) {
        const float* w  = (layer < 7) ? exp_w + (size_t)layer * 3 * 256 * 512
                                      : ref_w + (size_t)(layer - 7) * 3 * 256 * 512;
        const float* bi = (layer < 7) ? exp_b + layer * 512
                                      : ref_b + (layer - 7) * 512;
        int par = layer & 1;
        dim3 gA(LA / 64, 2, NB), gT(LT / 64, 2, NB);
        conv_glu_kernel<<<gA, 256>>>(0, par, w, bi, dils[layer], LA);
        conv_glu_kernel<<<gT, 256>>>(1, par, w, bi, dils[layer], LT);
    }

    norms_kernel<<<(NB*LA + NB*LT) / 8, 256>>>();
    dim3 gd(LA / 64, NB);
    distance_rowmax_kernel<<<gd, 256>>>(am, tm);
    topk_mlp_kernel<<<NB, 256>>>(ff1w, ff1b, ff2w, ff2b, out);
}

// round 7
// speedup vs baseline: 1.3944x; 1.3944x over previous
#include <cuda_runtime.h>
#include <cuda_bf16.h>
#include <cstdint>

#define NB 16
#define LA 1024
#define LT 512
#define DD 256

// ---------------- scratch (no allocation allowed) ----------------
__device__ float g_fA[2][NB*LA*DD];
__device__ float g_fT[2][NB*LT*DD];
__device__ __nv_bfloat16 g_hA[2][NB*LA*DD];
__device__ __nv_bfloat16 g_lA[2][NB*LA*DD];
__device__ __nv_bfloat16 g_hT[2][NB*LT*DD];
__device__ __nv_bfloat16 g_lT[2][NB*LT*DD];
__device__ __nv_bfloat16 g_wh[30u*512*256];   // [layer*3+k][permuted n][i] bf16 hi
__device__ __nv_bfloat16 g_wl[30u*512*256];   // lo
__device__ float g_norm[NB*LA + NB*LT];
__device__ float g_rowmax[NB*LA];

// ---------------- PTX helpers ----------------
__device__ __forceinline__ uint32_t smem_u32(const void* p) {
    uint32_t a;
    asm("{ .reg .u64 t; cvta.to.shared.u64 t, %1; cvt.u32.u64 %0, t; }" : "=r"(a) : "l"(p));
    return a;
}
__device__ __forceinline__ void cpa16(uint32_t dst, const void* src, uint32_t sz) {
    asm volatile("cp.async.cg.shared.global [%0], [%1], 16, %2;"
                 :: "r"(dst), "l"(src), "r"(sz) : "memory");
}
__device__ __forceinline__ void cpa_commit() {
    asm volatile("cp.async.commit_group;" ::: "memory");
}
__device__ __forceinline__ void ldsm4(uint32_t* r, uint32_t addr) {
    asm volatile("ldmatrix.sync.aligned.m8n8.x4.shared.b16 {%0,%1,%2,%3}, [%4];"
        : "=r"(r[0]), "=r"(r[1]), "=r"(r[2]), "=r"(r[3]) : "r"(addr));
}
__device__ __forceinline__ void mma16816(float* d, const uint32_t* a, const uint32_t* b) {
    asm volatile("mma.sync.aligned.m16n8k16.row.col.f32.bf16.bf16.f32 "
        "{%0,%1,%2,%3}, {%4,%5,%6,%7}, {%8,%9}, {%0,%1,%2,%3};"
        : "+f"(d[0]), "+f"(d[1]), "+f"(d[2]), "+f"(d[3])
        : "r"(a[0]), "r"(a[1]), "r"(a[2]), "r"(a[3]), "r"(b[0]), "r"(b[1]));
}

// ---------------- f32x2 helpers (distance kernel) ----------------
__device__ __forceinline__ unsigned long long bcast2(float a) {
    unsigned long long r; unsigned int u = __float_as_uint(a);
    asm("mov.b64 %0, {%1,%1};" : "=l"(r) : "r"(u));
    return r;
}
__device__ __forceinline__ unsigned long long pack2(float a, float b) {
    unsigned long long r;
    asm("mov.b64 %0, {%1,%2};" : "=l"(r) : "r"(__float_as_uint(a)), "r"(__float_as_uint(b)));
    return r;
}
__device__ __forceinline__ void ffma2(unsigned long long &acc,
                                      unsigned long long a, unsigned long long b) {
    asm("fma.rn.f32x2 %0, %1, %2, %0;" : "+l"(acc) : "l"(a), "l"(b));
}
__device__ __forceinline__ float2 unpk(unsigned long long v) {
    unsigned int lo, hi;
    asm("mov.b64 {%0,%1}, %2;" : "=r"(lo), "=r"(hi) : "l"(v));
    return make_float2(__uint_as_float(lo), __uint_as_float(hi));
}

// ---------------- weight prep: transpose + permute + bf16 hi/lo split ----------------
// dest layout: [kk][p][i], p = GLU-paired permutation:
//   orig a-col n(<256): p = (n>>6)*128 + (n&63)
//   orig g-col 256+c :  p = (c>>6)*128 + 64 + (c&63)
__global__ void wprep_kernel(const float* __restrict__ exp_w, const float* __restrict__ ref_w)
{
    size_t id = (size_t)blockIdx.x * 256 + threadIdx.x;   // < 30*512*256
    int i  = (int)(id & 255);
    int n  = (int)((id >> 8) & 511);
    int kk = (int)(id >> 17);                              // layer*3+k, 0..29
    const float* w = (kk < 21) ? exp_w + (size_t)kk * 256 * 512
                               : ref_w + (size_t)(kk - 21) * 256 * 512;
    float v = w[(size_t)i * 512 + n];
    int p;
    if (n < 256) { int q = n >> 6; p = q * 128 + (n & 63); }
    else         { int c = n - 256; int q = c >> 6; p = q * 128 + 64 + (c & 63); }
    size_t dst = ((size_t)kk * 512 + p) * 256 + i;
    __nv_bfloat16 h = __float2bfloat16(v);
    g_wh[dst] = h;
    g_wl[dst] = __float2bfloat16(v - __bfloat162float(h));
}

// ---------------- embedding gather (fp32 + bf16 hi/lo) ----------------
__global__ void embed_kernel(const int* __restrict__ aw, const int* __restrict__ tw,
                             const float* __restrict__ emb)
{
    int row = blockIdx.x;
    int t   = threadIdx.x;        // 64 threads x float4
    const float4* src; float4* dst; __nv_bfloat16 *h, *l;
    if (row < NB*LA) {
        src = (const float4*)(emb + (size_t)aw[row] * DD);
        size_t e = (size_t)row * DD;
        dst = (float4*)(g_fA[0] + e); h = g_hA[0] + e; l = g_lA[0] + e;
    } else {
        int r = row - NB*LA;
        src = (const float4*)(emb + (size_t)tw[r] * DD);
        size_t e = (size_t)r * DD;
        dst = (float4*)(g_fT[0] + e); h = g_hT[0] + e; l = g_lT[0] + e;
    }
    float4 v = src[t]; dst[t] = v;
    float vs[4] = {v.x, v.y, v.z, v.w};
    int i0 = t * 4;
#pragma unroll
    for (int qq = 0; qq < 4; qq++) {
        __nv_bfloat16 hh = __float2bfloat16(vs[qq]);
        h[i0+qq] = hh;
        l[i0+qq] = __float2bfloat16(vs[qq] - __bfloat162float(hh));
    }
}

// ---------------- mma.sync conv + GLU + residual ----------------
// CTA: 128 positions x 128 (permuted) out-cols. 256 thr = 8 warps (4 M x 2 N).
// Warp tile 32x64. K staged in 32-feature chunks, 24 stages, cp.async dbl-buffered.
// 3-pass bf16 hi/lo split: Ah*Bh + Ah*Bl + Al*Bh, fp32 accum.
// smem per stage: Ah|Al|Bh|Bl, each 128 rows x 32 bf16 @ stride 80B = 10240B.
#define STG     40960u
#define OFF_AL  10240u
#define OFF_BH  20480u
#define OFF_BL  30720u
#define CONV_SMEM (2u*STG)

__global__ __launch_bounds__(256, 2)
void conv_mma(int layer, int par, int dil, const float* __restrict__ bias)
{
    extern __shared__ char smem[];
    const uint32_t sb = smem_u32(smem);
    const int tid = threadIdx.x;

    int id = blockIdx.x;
    const int q = id & 3;
    int tile = id >> 2;
    int seq, b, l0, L;
    if (tile < 128) { seq = 0; b = tile >> 3; l0 = (tile & 7) << 7; L = LA; }
    else { tile -= 128; seq = 1; b = tile >> 2; l0 = (tile & 3) << 7; L = LT; }

    const float* xin; float* xout;
    const __nv_bfloat16 *xh, *xl; __nv_bfloat16 *oh, *ol;
    if (seq == 0) {
        xin = g_fA[par]; xout = g_fA[1-par];
        xh = g_hA[par]; xl = g_lA[par]; oh = g_hA[1-par]; ol = g_lA[1-par];
    } else {
        xin = g_fT[par]; xout = g_fT[1-par];
        xh = g_hT[par]; xl = g_lT[par]; oh = g_hT[1-par]; ol = g_lT[1-par];
    }

    const size_t wbase = (size_t)layer * 3 * 512 * 256;
    const int r0i = tid >> 2;       // cp.async row base (2 rows/thread: +0, +64)
    const int ci  = tid & 3;        // 16B column within 64B row payload

    // ---- stage issue macro ----
#define ISSUE(sn) do {                                                          \
        int k_ = (sn) >> 3, j0_ = ((sn) & 7) << 5;                              \
        uint32_t bufo_ = sb + (uint32_t)((sn) & 1) * STG;                       \
        int lb_ = l0 + (k_ - 1) * dil;                                          \
        _Pragma("unroll")                                                       \
        for (int i_ = 0; i_ < 2; ++i_) {                                        \
            int r_ = r0i + (i_ << 6);                                           \
            int l_ = lb_ + r_;                                                  \
            uint32_t dA_ = bufo_ + (uint32_t)(r_ * 80 + ci * 16);               \
            uint32_t ok_ = (l_ >= 0 && l_ < L) ? 16u : 0u;                      \
            size_t ea_ = ((size_t)b * L + (ok_ ? l_ : 0)) * 256 + j0_ + (ci<<3);\
            cpa16(dA_,          xh + ea_, ok_);                                 \
            cpa16(dA_ + OFF_AL, xl + ea_, ok_);                                 \
            size_t eb_ = wbase + ((size_t)(k_ * 512 + q * 128 + r_)) * 256      \
                         + j0_ + (ci << 3);                                     \
            cpa16(dA_ + OFF_BH, g_wh + eb_, 16u);                               \
            cpa16(dA_ + OFF_BL, g_wl + eb_, 16u);                               \
        }                                                                       \
        cpa_commit();                                                           \
    } while (0)

    float acc[2][8][4];
#pragma unroll
    for (int mt = 0; mt < 2; ++mt)
#pragma unroll
        for (int nt = 0; nt < 8; ++nt)
#pragma unroll
            for (int e = 0; e < 4; ++e) acc[mt][nt][e] = 0.f;

    const int lane = tid & 31, warp = tid >> 5;
    const int mw = warp >> 1, nw = warp & 1;
    const uint32_t aA_l = (uint32_t)((mw*32 + (lane & 15)) * 80 + (lane >> 4) * 16);
    const uint32_t aB_l = (uint32_t)((nw*64 + ((lane & 7) | ((lane >> 4) << 3))) * 80
                                    + ((lane >> 3) & 1) * 16);

    ISSUE(0);
    for (int s = 0; s < 24; ++s) {
        if (s < 23) {
            ISSUE(s + 1);
            asm volatile("cp.async.wait_group 1;" ::: "memory");
        } else {
            asm volatile("cp.async.wait_group 0;" ::: "memory");
        }
        __syncthreads();
        const uint32_t bufo = sb + (uint32_t)(s & 1) * STG;
#pragma unroll
        for (int ks = 0; ks < 2; ++ks) {
            uint32_t ah[2][4], al[2][4];
#pragma unroll
            for (int mt = 0; mt < 2; ++mt) {
                ldsm4(ah[mt], bufo +          aA_l + mt*1280u + ks*32u);
                ldsm4(al[mt], bufo + OFF_AL + aA_l + mt*1280u + ks*32u);
            }
#pragma unroll
            for (int ng = 0; ng < 4; ++ng) {
                uint32_t bh[4], bl[4];
                ldsm4(bh, bufo + OFF_BH + aB_l + ng*1280u + ks*32u);
                ldsm4(bl, bufo + OFF_BL + aB_l + ng*1280u + ks*32u);
#pragma unroll
                for (int mt = 0; mt < 2; ++mt) {
                    mma16816(acc[mt][2*ng],   ah[mt], bh);
                    mma16816(acc[mt][2*ng+1], ah[mt], bh + 2);
                }
#pragma unroll
                for (int mt = 0; mt < 2; ++mt) {
                    mma16816(acc[mt][2*ng],   ah[mt], bl);
                    mma16816(acc[mt][2*ng+1], ah[mt], bl + 2);
                }
#pragma unroll
                for (int mt = 0; mt < 2; ++mt) {
                    mma16816(acc[mt][2*ng],   al[mt], bh);
                    mma16816(acc[mt][2*ng+1], al[mt], bh + 2);
                }
            }
        }
        __syncthreads();
    }
#undef ISSUE

    // ---- epilogue: dump accums to smem, then fused bias+GLU+residual ----
    float* Ds = (float*)smem;     // [128][132]
#pragma unroll
    for (int mt = 0; mt < 2; ++mt)
#pragma unroll
        for (int nt = 0; nt < 8; ++nt) {
            int r = mw*32 + mt*16 + (lane >> 2);
            int c = nw*64 + nt*8 + ((lane & 3) << 1);
            *(float2*)&Ds[r * 132 + c]       = make_float2(acc[mt][nt][0], acc[mt][nt][1]);
            *(float2*)&Ds[(r + 8) * 132 + c] = make_float2(acc[mt][nt][2], acc[mt][nt][3]);
        }
    __syncthreads();

    const int n  = tid & 63, pg = tid >> 6;
    const int ch = q * 64 + n;
    const float ba = bias[ch], bg = bias[256 + ch];
#pragma unroll 4
    for (int i = 0; i < 32; ++i) {
        int p = pg + (i << 2);
        float a = Ds[p * 132 + n] + ba;
        float g = Ds[p * 132 + 64 + n] + bg;
        size_t gi = (((size_t)b * L) + l0 + p) * 256 + ch;
        float y = xin[gi] + a / (1.0f + __expf(-g));
        xout[gi] = y;
        __nv_bfloat16 h = __float2bfloat16(y);
        oh[gi] = h;
        ol[gi] = __float2bfloat16(y - __bfloat162float(h));
    }
}

// ---------------- squared norms ----------------
__global__ void norms_kernel()
{
    int gwarp = (blockIdx.x * blockDim.x + threadIdx.x) >> 5;
    int lane  = threadIdx.x & 31;
    const int total = NB*LA + NB*LT;
    if (gwarp >= total) return;
    const float* row = (gwarp < NB*LA) ? (g_fA[0] + (size_t)gwarp * DD)
                                       : (g_fT[0] + (size_t)(gwarp - NB*LA) * DD);
    const float4* r4 = (const float4*)row;
    float s = 0.f;
#pragma unroll
    for (int i = 0; i < 2; ++i) {
        float4 v = r4[lane + i * 32];
        s += v.x*v.x + v.y*v.y + v.z*v.z + v.w*v.w;
    }
#pragma unroll
    for (int off = 16; off > 0; off >>= 1) s += __shfl_xor_sync(0xffffffffu, s, off);
    if (lane == 0) g_norm[gwarp] = s;
}

// ---------------- pairwise distance + row-max (f32x2) ----------------
__global__ __launch_bounds__(256)
void distance_rowmax_kernel(const float* __restrict__ am, const float* __restrict__ tm)
{
    const int b  = blockIdx.y;
    const int a0 = blockIdx.x * 64;
    const float* art = g_fA[0] + (size_t)b * LA * DD;
    const float* tpl = g_fT[0] + (size_t)b * LT * DD;
    const float* a2  = g_norm + b * LA;
    const float* t2  = g_norm + NB*LA + b * LT;

    __shared__ float Asx[64*33];
    __shared__ float Tsx[64*33];
    __shared__ float red[64*17];

    const int tid = threadIdx.x;
    const int pg  = tid & 15;
    const int tg  = tid >> 4;
    const int jl  = tid & 31, mb = tid >> 5;

    float rmax[4] = {0.f, 0.f, 0.f, 0.f};

    for (int tt = 0; tt < LT; tt += 64) {
        unsigned long long acc2[4][2];
#pragma unroll
        for (int i = 0; i < 4; i++) { acc2[i][0] = 0ull; acc2[i][1] = 0ull; }

        for (int d0 = 0; d0 < DD; d0 += 32) {
            __syncthreads();
#pragma unroll
            for (int it = 0; it < 8; ++it) {
                int m = mb + it * 8;
                Asx[m * 33 + jl] = art[(size_t)(a0 + m) * DD + d0 + jl];
                Tsx[m * 33 + jl] = tpl[(size_t)(tt + m) * DD + d0 + jl];
            }
            __syncthreads();
#pragma unroll 8
            for (int j = 0; j < 32; ++j) {
                unsigned long long tp0 = pack2(Tsx[(tg*4 + 0) * 33 + j], Tsx[(tg*4 + 1) * 33 + j]);
                unsigned long long tp1 = pack2(Tsx[(tg*4 + 2) * 33 + j], Tsx[(tg*4 + 3) * 33 + j]);
#pragma unroll
                for (int i = 0; i < 4; i++) {
                    unsigned long long ap = bcast2(Asx[(pg*4 + i) * 33 + j]);
                    ffma2(acc2[i][0], ap, tp0);
                    ffma2(acc2[i][1], ap, tp1);
                }
            }
        }
#pragma unroll
        for (int i = 0; i < 4; i++) {
            int a = a0 + pg*4 + i;
            float an = a2[a];
            float dots[4];
            float2 q01 = unpk(acc2[i][0]), q23 = unpk(acc2[i][1]);
            dots[0] = q01.x; dots[1] = q01.y; dots[2] = q23.x; dots[3] = q23.y;
#pragma unroll
            for (int qq = 0; qq < 4; qq++) {
                int t = tt + tg*4 + qq;
                float dist = fmaxf(an + t2[t] - 2.0f * dots[qq], 0.0f);
                float val  = __expf(-dist) * tm[b * LT + t];
                rmax[i] = fmaxf(rmax[i], val);
            }
        }
    }
    __syncthreads();
#pragma unroll
    for (int i = 0; i < 4; i++) red[(pg*4 + i) * 17 + tg] = rmax[i];
    __syncthreads();
    if (tid < 64) {
        float m = 0.f;
#pragma unroll
        for (int qq = 0; qq < 16; qq++) m = fmaxf(m, red[tid * 17 + qq]);
        g_rowmax[b * LA + a0 + tid] = m * am[b * LA + a0 + tid];
    }
}

// ---------------- top-10 + tiny MLP ----------------
__global__ void topk_mlp_kernel(const float* __restrict__ ff1w, const float* __restrict__ ff1b,
                                const float* __restrict__ ff2w, const float* __restrict__ ff2b,
                                float* __restrict__ out)
{
    const int b = blockIdx.x;
    __shared__ float vals[1024];
    __shared__ float rv[256];
    __shared__ int   ri[256];
    __shared__ float top[10];
    __shared__ float hbuf[10];
    const int tid = threadIdx.x;

    for (int i = tid; i < 1024; i += 256) vals[i] = g_rowmax[b * LA + i];
    __syncthreads();

    for (int it = 0; it < 10; ++it) {
        float best = -1e30f; int bi = 0;
        for (int i = tid; i < 1024; i += 256) {
            float v = vals[i];
            if (v > best) { best = v; bi = i; }
        }
        rv[tid] = best; ri[tid] = bi;
        __syncthreads();
        for (int s = 128; s > 0; s >>= 1) {
            if (tid < s) {
                float ov = rv[tid + s]; int oi = ri[tid + s];
                if (ov > rv[tid] || (ov == rv[tid] && oi < ri[tid])) { rv[tid] = ov; ri[tid] = oi; }
            }
            __syncthreads();
        }
        if (tid == 0) { top[it] = rv[0]; vals[ri[0]] = -1e30f; }
        __syncthreads();
    }

    if (tid < 10) {
        float h = ff1b[tid];
#pragma unroll
        for (int i = 0; i < 10; i++) h += top[i] * ff1w[i * 10 + tid];
        hbuf[tid] = fmaxf(h, 0.f);
    }
    __syncthreads();
    if (tid == 0) {
        float o = ff2b[0];
#pragma unroll
        for (int i = 0; i < 10; i++) o += hbuf[i] * ff2w[i];
        out[b] = o;
    }
}

// ---------------- launch ----------------
extern "C" void kernel_launch(void* const* d_in, const int* in_sizes, int n_in,
                              void* d_out, int out_size)
{
    const int*   aw    = (const int*)  d_in[0];
    const int*   tw    = (const int*)  d_in[2];
    const float* am    = (const float*)d_in[4];
    const float* tm    = (const float*)d_in[5];
    const float* emb   = (const float*)d_in[6];
    const float* exp_w = (const float*)d_in[7];
    const float* exp_b = (const float*)d_in[8];
    const float* ref_w = (const float*)d_in[9];
    const float* ref_b = (const float*)d_in[10];
    const float* ff1w  = (const float*)d_in[11];
    const float* ff1b  = (const float*)d_in[12];
    const float* ff2w  = (const float*)d_in[13];
    const float* ff2b  = (const float*)d_in[14];
    float* out = (float*)d_out;

    cudaFuncSetAttribute(conv_mma, cudaFuncAttributeMaxDynamicSharedMemorySize, CONV_SMEM);

    wprep_kernel<<<15360, 256>>>(exp_w, ref_w);
    embed_kernel<<<NB*LA + NB*LT, 64>>>(aw, tw, emb);

    const int dils[10] = {1, 2, 4, 8, 16, 32, 32, 1, 1, 1};
    for (int layer = 0; layer < 10; ++layer) {
        const float* bi = (layer < 7) ? exp_b + layer * 512
                                      : ref_b + (layer - 7) * 512;
        conv_mma<<<768, 256, CONV_SMEM>>>(layer, layer & 1, dils[layer], bi);
    }

    norms_kernel<<<(NB*LA + NB*LT) / 8, 256>>>();
    dim3 gd(LA / 64, NB);
    distance_rowmax_kernel<<<gd, 256>>>(am, tm);
    topk_mlp_kernel<<<NB, 256>>>(ff1w, ff1b, ff2w, ff2b, out);
}

// round 9
// speedup vs baseline: 2.3913x; 1.7150x over previous
#include <cuda_runtime.h>
#include <cuda_bf16.h>
#include <cstdint>

#define NB 16
#define LA 1024
#define LT 512
#define DD 256

// ---------------- scratch (no allocation allowed) ----------------
__device__ float g_fA[2][NB*LA*DD];
__device__ float g_fT[2][NB*LT*DD];
__device__ __nv_bfloat16 g_hA[2][NB*LA*DD];
__device__ __nv_bfloat16 g_lA[2][NB*LA*DD];
__device__ __nv_bfloat16 g_hT[2][NB*LT*DD];
__device__ __nv_bfloat16 g_lT[2][NB*LT*DD];
__device__ __nv_bfloat16 g_wh[30u*512*256];   // [layer*3+k][permuted n][i] bf16 hi
__device__ __nv_bfloat16 g_wl[30u*512*256];   // lo
__device__ float g_norm[NB*LA + NB*LT];
__device__ float g_rowmax[NB*LA];

// ---------------- PTX helpers ----------------
__device__ __forceinline__ uint32_t smem_u32(const void* p) {
    uint32_t a;
    asm("{ .reg .u64 t; cvta.to.shared.u64 t, %1; cvt.u32.u64 %0, t; }" : "=r"(a) : "l"(p));
    return a;
}
__device__ __forceinline__ void cpa16(uint32_t dst, const void* src, uint32_t sz) {
    asm volatile("cp.async.cg.shared.global [%0], [%1], 16, %2;"
                 :: "r"(dst), "l"(src), "r"(sz) : "memory");
}
__device__ __forceinline__ void cpa_commit() {
    asm volatile("cp.async.commit_group;" ::: "memory");
}
__device__ __forceinline__ void ldsm4(uint32_t* r, uint32_t addr) {
    asm volatile("ldmatrix.sync.aligned.m8n8.x4.shared.b16 {%0,%1,%2,%3}, [%4];"
        : "=r"(r[0]), "=r"(r[1]), "=r"(r[2]), "=r"(r[3]) : "r"(addr));
}
__device__ __forceinline__ void mma16816(float* d, const uint32_t* a, const uint32_t* b) {
    asm volatile("mma.sync.aligned.m16n8k16.row.col.f32.bf16.bf16.f32 "
        "{%0,%1,%2,%3}, {%4,%5,%6,%7}, {%8,%9}, {%0,%1,%2,%3};"
        : "+f"(d[0]), "+f"(d[1]), "+f"(d[2]), "+f"(d[3])
        : "r"(a[0]), "r"(a[1]), "r"(a[2]), "r"(a[3]), "r"(b[0]), "r"(b[1]));
}

// ---------------- f32x2 helpers (distance kernel) ----------------
__device__ __forceinline__ unsigned long long bcast2(float a) {
    unsigned long long r; unsigned int u = __float_as_uint(a);
    asm("mov.b64 %0, {%1,%1};" : "=l"(r) : "r"(u));
    return r;
}
__device__ __forceinline__ unsigned long long pack2(float a, float b) {
    unsigned long long r;
    asm("mov.b64 %0, {%1,%2};" : "=l"(r) : "r"(__float_as_uint(a)), "r"(__float_as_uint(b)));
    return r;
}
__device__ __forceinline__ void ffma2(unsigned long long &acc,
                                      unsigned long long a, unsigned long long b) {
    asm("fma.rn.f32x2 %0, %1, %2, %0;" : "+l"(acc) : "l"(a), "l"(b));
}
__device__ __forceinline__ float2 unpk(unsigned long long v) {
    unsigned int lo, hi;
    asm("mov.b64 {%0,%1}, %2;" : "=r"(lo), "=r"(hi) : "l"(v));
    return make_float2(__uint_as_float(lo), __uint_as_float(hi));
}

// ---------------- weight prep: transpose + permute + bf16 hi/lo split ----------------
__global__ void wprep_kernel(const float* __restrict__ exp_w, const float* __restrict__ ref_w)
{
    size_t id = (size_t)blockIdx.x * 256 + threadIdx.x;   // < 30*512*256
    int i  = (int)(id & 255);
    int n  = (int)((id >> 8) & 511);
    int kk = (int)(id >> 17);                              // layer*3+k, 0..29
    const float* w = (kk < 21) ? exp_w + (size_t)kk * 256 * 512
                               : ref_w + (size_t)(kk - 21) * 256 * 512;
    float v = w[(size_t)i * 512 + n];
    int p;
    if (n < 256) { int q = n >> 6; p = q * 128 + (n & 63); }
    else         { int c = n - 256; int q = c >> 6; p = q * 128 + 64 + (c & 63); }
    size_t dst = ((size_t)kk * 512 + p) * 256 + i;
    __nv_bfloat16 h = __float2bfloat16(v);
    g_wh[dst] = h;
    g_wl[dst] = __float2bfloat16(v - __bfloat162float(h));
}

// ---------------- embedding gather (fp32 + bf16 hi/lo) ----------------
__global__ void embed_kernel(const int* __restrict__ aw, const int* __restrict__ tw,
                             const float* __restrict__ emb)
{
    int row = blockIdx.x;
    int t   = threadIdx.x;        // 64 threads x float4
    const float4* src; float4* dst; __nv_bfloat16 *h, *l;
    if (row < NB*LA) {
        src = (const float4*)(emb + (size_t)aw[row] * DD);
        size_t e = (size_t)row * DD;
        dst = (float4*)(g_fA[0] + e); h = g_hA[0] + e; l = g_lA[0] + e;
    } else {
        int r = row - NB*LA;
        src = (const float4*)(emb + (size_t)tw[r] * DD);
        size_t e = (size_t)r * DD;
        dst = (float4*)(g_fT[0] + e); h = g_hT[0] + e; l = g_lT[0] + e;
    }
    float4 v = src[t]; dst[t] = v;
    float vs[4] = {v.x, v.y, v.z, v.w};
    int i0 = t * 4;
#pragma unroll
    for (int qq = 0; qq < 4; qq++) {
        __nv_bfloat16 hh = __float2bfloat16(vs[qq]);
        h[i0+qq] = hh;
        l[i0+qq] = __float2bfloat16(vs[qq] - __bfloat162float(hh));
    }
}

// ---------------- mma.sync conv + GLU + residual ----------------
// CTA: 128 positions x 128 (permuted) out-cols. 256 thr = 8 warps (4 M x 2 N).
// 24 K-stages of 32 features, 3-stage cp.async ring, ONE barrier per stage.
// Tiles: 128 rows x 64B, XOR swizzle: chunk' = chunk ^ ((row>>1)&3).
// 3-pass bf16 hi/lo split: Ah*Bh + Ah*Bl + Al*Bh, fp32 accum.
#define STG3    32768u
#define OFF_AL  8192u
#define OFF_BH  16384u
#define OFF_BL  24576u
#define CONV_SMEM (3u*STG3)

__global__ __launch_bounds__(256, 2)
void conv_mma(int layer, int par, int dil, const float* __restrict__ bias)
{
    extern __shared__ char smem[];
    const uint32_t sb = smem_u32(smem);
    const int tid = threadIdx.x;

    int id = blockIdx.x;
    const int q = id & 3;
    int tile = id >> 2;
    int seq, b, l0, L;
    if (tile < 128) { seq = 0; b = tile >> 3; l0 = (tile & 7) << 7; L = LA; }
    else { tile -= 128; seq = 1; b = tile >> 2; l0 = (tile & 3) << 7; L = LT; }

    const float* xin; float* xout;
    const __nv_bfloat16 *xh, *xl; __nv_bfloat16 *oh, *ol;
    if (seq == 0) {
        xin = g_fA[par]; xout = g_fA[1-par];
        xh = g_hA[par]; xl = g_lA[par]; oh = g_hA[1-par]; ol = g_lA[1-par];
    } else {
        xin = g_fT[par]; xout = g_fT[1-par];
        xh = g_hT[par]; xl = g_lT[par]; oh = g_hT[1-par]; ol = g_lT[1-par];
    }

    const size_t wbase = (size_t)layer * 3 * 512 * 256;
    const int r0i = tid >> 2;       // cp.async row base (2 rows/thread: +0, +64)
    const int ci  = tid & 3;        // 16B chunk within 64B row

    // ---- stage issue macro (swizzled 64B rows) ----
#define ISSUE(sn, bufo_) do {                                                   \
        int k_ = (sn) >> 3, j0_ = ((sn) & 7) << 5;                              \
        int lb_ = l0 + (k_ - 1) * dil;                                          \
        _Pragma("unroll")                                                       \
        for (int i_ = 0; i_ < 2; ++i_) {                                        \
            int r_ = r0i + (i_ << 6);                                           \
            int l_ = lb_ + r_;                                                  \
            uint32_t dA_ = (bufo_) + (uint32_t)(r_ * 64                         \
                           + ((ci ^ ((r_ >> 1) & 3)) << 4));                    \
            uint32_t ok_ = (l_ >= 0 && l_ < L) ? 16u : 0u;                      \
            size_t ea_ = ((size_t)b * L + (ok_ ? l_ : 0)) * 256 + j0_ + (ci<<3);\
            cpa16(dA_,          xh + ea_, ok_);                                 \
            cpa16(dA_ + OFF_AL, xl + ea_, ok_);                                 \
            size_t eb_ = wbase + ((size_t)(k_ * 512 + q * 128 + r_)) * 256      \
                         + j0_ + (ci << 3);                                     \
            cpa16(dA_ + OFF_BH, g_wh + eb_, 16u);                               \
            cpa16(dA_ + OFF_BL, g_wl + eb_, 16u);                               \
        }                                                                       \
        cpa_commit();                                                           \
    } while (0)

    float acc[2][8][4];
#pragma unroll
    for (int mt = 0; mt < 2; ++mt)
#pragma unroll
        for (int nt = 0; nt < 8; ++nt)
#pragma unroll
            for (int e = 0; e < 4; ++e) acc[mt][nt][e] = 0.f;

    const int lane = tid & 31, warp = tid >> 5;
    const int mw = warp >> 1, nw = warp & 1;
    // ldmatrix per-lane offsets (relative to tile base), ks=0; ks=1 == addr ^ 32
    uint32_t offA[2], offB[4];
    {
        const int cA0 = lane >> 4;
#pragma unroll
        for (int mt = 0; mt < 2; ++mt) {
            int r = mw*32 + mt*16 + (lane & 15);
            offA[mt] = (uint32_t)(r * 64 + ((cA0 ^ ((r >> 1) & 3)) << 4));
        }
        const int rBl = (lane & 7) | ((lane >> 4) << 3);
        const int cB0 = (lane >> 3) & 1;
#pragma unroll
        for (int ng = 0; ng < 4; ++ng) {
            int r = nw*64 + ng*16 + rBl;
            offB[ng] = (uint32_t)(r * 64 + ((cB0 ^ ((r >> 1) & 3)) << 4));
        }
    }

    ISSUE(0, sb);
    ISSUE(1, sb + STG3);
    for (int s = 0; s < 24; ++s) {
        if (s < 23) asm volatile("cp.async.wait_group 1;" ::: "memory");
        else        asm volatile("cp.async.wait_group 0;" ::: "memory");
        __syncthreads();
        if (s < 22) {
            uint32_t ibuf = sb + (uint32_t)((s + 2) % 3) * STG3;
            ISSUE(s + 2, ibuf);
        }
        const uint32_t bufo = sb + (uint32_t)(s % 3) * STG3;
#pragma unroll
        for (int ks = 0; ks < 2; ++ks) {
            const uint32_t kx = (uint32_t)(ks << 5);
            uint32_t ah[2][4], al[2][4];
#pragma unroll
            for (int mt = 0; mt < 2; ++mt) {
                ldsm4(ah[mt], (bufo +          offA[mt]) ^ kx);
                ldsm4(al[mt], (bufo + OFF_AL + offA[mt]) ^ kx);
            }
#pragma unroll
            for (int ng = 0; ng < 4; ++ng) {
                uint32_t bh[4], bl[4];
                ldsm4(bh, (bufo + OFF_BH + offB[ng]) ^ kx);
                ldsm4(bl, (bufo + OFF_BL + offB[ng]) ^ kx);
#pragma unroll
                for (int mt = 0; mt < 2; ++mt) {
                    mma16816(acc[mt][2*ng],   ah[mt], bh);
                    mma16816(acc[mt][2*ng+1], ah[mt], bh + 2);
                }
#pragma unroll
                for (int mt = 0; mt < 2; ++mt) {
                    mma16816(acc[mt][2*ng],   ah[mt], bl);
                    mma16816(acc[mt][2*ng+1], ah[mt], bl + 2);
                }
#pragma unroll
                for (int mt = 0; mt < 2; ++mt) {
                    mma16816(acc[mt][2*ng],   al[mt], bh);
                    mma16816(acc[mt][2*ng+1], al[mt], bh + 2);
                }
            }
        }
    }
#undef ISSUE
    __syncthreads();   // all reads done before epilogue overwrites smem

    // ---- epilogue: dump accums to smem, then fused bias+GLU+residual ----
    float* Ds = (float*)smem;     // [128][132]
#pragma unroll
    for (int mt = 0; mt < 2; ++mt)
#pragma unroll
        for (int nt = 0; nt < 8; ++nt) {
            int r = mw*32 + mt*16 + (lane >> 2);
            int c = nw*64 + nt*8 + ((lane & 3) << 1);
            *(float2*)&Ds[r * 132 + c]       = make_float2(acc[mt][nt][0], acc[mt][nt][1]);
            *(float2*)&Ds[(r + 8) * 132 + c] = make_float2(acc[mt][nt][2], acc[mt][nt][3]);
        }
    __syncthreads();

    const int n  = tid & 63, pg = tid >> 6;
    const int ch = q * 64 + n;
    const float ba = bias[ch], bg = bias[256 + ch];
#pragma unroll 4
    for (int i = 0; i < 32; ++i) {
        int p = pg + (i << 2);
        float a = Ds[p * 132 + n] + ba;
        float g = Ds[p * 132 + 64 + n] + bg;
        size_t gi = (((size_t)b * L) + l0 + p) * 256 + ch;
        float y = xin[gi] + a / (1.0f + __expf(-g));
        xout[gi] = y;
        __nv_bfloat16 h = __float2bfloat16(y);
        oh[gi] = h;
        ol[gi] = __float2bfloat16(y - __bfloat162float(h));
    }
}

// ---------------- squared norms ----------------
__global__ void norms_kernel()
{
    int gwarp = (blockIdx.x * blockDim.x + threadIdx.x) >> 5;
    int lane  = threadIdx.x & 31;
    const int total = NB*LA + NB*LT;
    if (gwarp >= total) return;
    const float* row = (gwarp < NB*LA) ? (g_fA[0] + (size_t)gwarp * DD)
                                       : (g_fT[0] + (size_t)(gwarp - NB*LA) * DD);
    const float4* r4 = (const float4*)row;
    float s = 0.f;
#pragma unroll
    for (int i = 0; i < 2; ++i) {
        float4 v = r4[lane + i * 32];
        s += v.x*v.x + v.y*v.y + v.z*v.z + v.w*v.w;
    }
#pragma unroll
    for (int off = 16; off > 0; off >>= 1) s += __shfl_xor_sync(0xffffffffu, s, off);
    if (lane == 0) g_norm[gwarp] = s;
}

// ---------------- pairwise distance + row-max (f32x2) ----------------
__global__ __launch_bounds__(256)
void distance_rowmax_kernel(const float* __restrict__ am, const float* __restrict__ tm)
{
    const int b  = blockIdx.y;
    const int a0 = blockIdx.x * 64;
    const float* art = g_fA[0] + (size_t)b * LA * DD;
    const float* tpl = g_fT[0] + (size_t)b * LT * DD;
    const float* a2  = g_norm + b * LA;
    const float* t2  = g_norm + NB*LA + b * LT;

    __shared__ float Asx[64*33];
    __shared__ float Tsx[64*33];
    __shared__ float red[64*17];

    const int tid = threadIdx.x;
    const int pg  = tid & 15;
    const int tg  = tid >> 4;
    const int jl  = tid & 31, mb = tid >> 5;

    float rmax[4] = {0.f, 0.f, 0.f, 0.f};

    for (int tt = 0; tt < LT; tt += 64) {
        unsigned long long acc2[4][2];
#pragma unroll
        for (int i = 0; i < 4; i++) { acc2[i][0] = 0ull; acc2[i][1] = 0ull; }

        for (int d0 = 0; d0 < DD; d0 += 32) {
            __syncthreads();
#pragma unroll
            for (int it = 0; it < 8; ++it) {
                int m = mb + it * 8;
                Asx[m * 33 + jl] = art[(size_t)(a0 + m) * DD + d0 + jl];
                Tsx[m * 33 + jl] = tpl[(size_t)(tt + m) * DD + d0 + jl];
            }
            __syncthreads();
#pragma unroll 8
            for (int j = 0; j < 32; ++j) {
                unsigned long long tp0 = pack2(Tsx[(tg*4 + 0) * 33 + j], Tsx[(tg*4 + 1) * 33 + j]);
                unsigned long long tp1 = pack2(Tsx[(tg*4 + 2) * 33 + j], Tsx[(tg*4 + 3) * 33 + j]);
#pragma unroll
                for (int i = 0; i < 4; i++) {
                    unsigned long long ap = bcast2(Asx[(pg*4 + i) * 33 + j]);
                    ffma2(acc2[i][0], ap, tp0);
                    ffma2(acc2[i][1], ap, tp1);
                }
            }
        }
#pragma unroll
        for (int i = 0; i < 4; i++) {
            int a = a0 + pg*4 + i;
            float an = a2[a];
            float dots[4];
            float2 q01 = unpk(acc2[i][0]), q23 = unpk(acc2[i][1]);
            dots[0] = q01.x; dots[1] = q01.y; dots[2] = q23.x; dots[3] = q23.y;
#pragma unroll
            for (int qq = 0; qq < 4; qq++) {
                int t = tt + tg*4 + qq;
                float dist = fmaxf(an + t2[t] - 2.0f * dots[qq], 0.0f);
                float val  = __expf(-dist) * tm[b * LT + t];
                rmax[i] = fmaxf(rmax[i], val);
            }
        }
    }
    __syncthreads();
#pragma unroll
    for (int i = 0; i < 4; i++) red[(pg*4 + i) * 17 + tg] = rmax[i];
    __syncthreads();
    if (tid < 64) {
        float m = 0.f;
#pragma unroll
        for (int qq = 0; qq < 16; qq++) m = fmaxf(m, red[tid * 17 + qq]);
        g_rowmax[b * LA + a0 + tid] = m * am[b * LA + a0 + tid];
    }
}

// ---------------- top-10 + tiny MLP ----------------
__global__ void topk_mlp_kernel(const float* __restrict__ ff1w, const float* __restrict__ ff1b,
                                const float* __restrict__ ff2w, const float* __restrict__ ff2b,
                                float* __restrict__ out)
{
    const int b = blockIdx.x;
    __shared__ float vals[1024];
    __shared__ float rv[256];
    __shared__ int   ri[256];
    __shared__ float top[10];
    __shared__ float hbuf[10];
    const int tid = threadIdx.x;

    for (int i = tid; i < 1024; i += 256) vals[i] = g_rowmax[b * LA + i];
    __syncthreads();

    for (int it = 0; it < 10; ++it) {
        float best = -1e30f; int bi = 0;
        for (int i = tid; i < 1024; i += 256) {
            float v = vals[i];
            if (v > best) { best = v; bi = i; }
        }
        rv[tid] = best; ri[tid] = bi;
        __syncthreads();
        for (int s = 128; s > 0; s >>= 1) {
            if (tid < s) {
                float ov = rv[tid + s]; int oi = ri[tid + s];
                if (ov > rv[tid] || (ov == rv[tid] && oi < ri[tid])) { rv[tid] = ov; ri[tid] = oi; }
            }
            __syncthreads();
        }
        if (tid == 0) { top[it] = rv[0]; vals[ri[0]] = -1e30f; }
        __syncthreads();
    }

    if (tid < 10) {
        float h = ff1b[tid];
#pragma unroll
        for (int i = 0; i < 10; i++) h += top[i] * ff1w[i * 10 + tid];
        hbuf[tid] = fmaxf(h, 0.f);
    }
    __syncthreads();
    if (tid == 0) {
        float o = ff2b[0];
#pragma unroll
        for (int i = 0; i < 10; i++) o += hbuf[i] * ff2w[i];
        out[b] = o;
    }
}

// ---------------- launch ----------------
extern "C" void kernel_launch(void* const* d_in, const int* in_sizes, int n_in,
                              void* d_out, int out_size)
{
    const int*   aw    = (const int*)  d_in[0];
    const int*   tw    = (const int*)  d_in[2];
    const float* am    = (const float*)d_in[4];
    const float* tm    = (const float*)d_in[5];
    const float* emb   = (const float*)d_in[6];
    const float* exp_w = (const float*)d_in[7];
    const float* exp_b = (const float*)d_in[8];
    const float* ref_w = (const float*)d_in[9];
    const float* ref_b = (const float*)d_in[10];
    const float* ff1w  = (const float*)d_in[11];
    const float* ff1b  = (const float*)d_in[12];
    const float* ff2w  = (const float*)d_in[13];
    const float* ff2b  = (const float*)d_in[14];
    float* out = (float*)d_out;

    cudaFuncSetAttribute(conv_mma, cudaFuncAttributeMaxDynamicSharedMemorySize, CONV_SMEM);

    wprep_kernel<<<15360, 256>>>(exp_w, ref_w);
    embed_kernel<<<NB*LA + NB*LT, 64>>>(aw, tw, emb);

    const int dils[10] = {1, 2, 4, 8, 16, 32, 32, 1, 1, 1};
    for (int layer = 0; layer < 10; ++layer) {
        const float* bi = (layer < 7) ? exp_b + layer * 512
                                      : ref_b + (layer - 7) * 512;
        conv_mma<<<768, 256, CONV_SMEM>>>(layer, layer & 1, dils[layer], bi);
    }

    norms_kernel<<<(NB*LA + NB*LT) / 8, 256>>>();
    dim3 gd(LA / 64, NB);
    distance_rowmax_kernel<<<gd, 256>>>(am, tm);
    topk_mlp_kernel<<<NB, 256>>>(ff1w, ff1b, ff2w, ff2b, out);
}

// round 11
// speedup vs baseline: 2.6224x; 1.0966x over previous
#include <cuda_runtime.h>
#include <cuda_bf16.h>
#include <cstdint>

#define NB 16
#define LA 1024
#define LT 512
#define DD 256

// ---------------- scratch (no allocation allowed) ----------------
__device__ float g_fA[2][NB*LA*DD];
__device__ float g_fT[2][NB*LT*DD];
__device__ __nv_bfloat16 g_hA[2][NB*LA*DD];
__device__ __nv_bfloat16 g_lA[2][NB*LA*DD];
__device__ __nv_bfloat16 g_hT[2][NB*LT*DD];
__device__ __nv_bfloat16 g_lT[2][NB*LT*DD];
__device__ __nv_bfloat16 g_wh[30u*512*256];   // [layer*3+k][permuted n][i] bf16 hi
__device__ __nv_bfloat16 g_wl[30u*512*256];   // lo
__device__ float g_norm[NB*LA + NB*LT];
__device__ float g_rowmax[NB*LA];

// ---------------- PTX helpers ----------------
__device__ __forceinline__ uint32_t smem_u32(const void* p) {
    uint32_t a;
    asm("{ .reg .u64 t; cvta.to.shared.u64 t, %1; cvt.u32.u64 %0, t; }" : "=r"(a) : "l"(p));
    return a;
}
__device__ __forceinline__ void cpa16(uint32_t dst, const void* src, uint32_t sz) {
    asm volatile("cp.async.cg.shared.global [%0], [%1], 16, %2;"
                 :: "r"(dst), "l"(src), "r"(sz) : "memory");
}
__device__ __forceinline__ void cpa_commit() {
    asm volatile("cp.async.commit_group;" ::: "memory");
}
__device__ __forceinline__ void ldsm4(uint32_t* r, uint32_t addr) {
    asm volatile("ldmatrix.sync.aligned.m8n8.x4.shared.b16 {%0,%1,%2,%3}, [%4];"
        : "=r"(r[0]), "=r"(r[1]), "=r"(r[2]), "=r"(r[3]) : "r"(addr));
}
__device__ __forceinline__ void mma16816(float* d, const uint32_t* a, const uint32_t* b) {
    asm volatile("mma.sync.aligned.m16n8k16.row.col.f32.bf16.bf16.f32 "
        "{%0,%1,%2,%3}, {%4,%5,%6,%7}, {%8,%9}, {%0,%1,%2,%3};"
        : "+f"(d[0]), "+f"(d[1]), "+f"(d[2]), "+f"(d[3])
        : "r"(a[0]), "r"(a[1]), "r"(a[2]), "r"(a[3]), "r"(b[0]), "r"(b[1]));
}

// ---------------- weight prep: tiled transpose + permute + bf16 hi/lo split ----------------
__global__ void wprep_kernel(const float* __restrict__ exp_w, const float* __restrict__ ref_w)
{
    __shared__ float ts[64][65];
    const int kk = blockIdx.z;            // 0..29 (layer*3+k)
    const int i0 = blockIdx.y * 64;       // input-channel tile
    const int n0 = blockIdx.x * 64;       // orig out-col tile (64-aligned -> contiguous p)
    const float* w = (kk < 21) ? exp_w + (size_t)kk * 256 * 512
                               : ref_w + (size_t)(kk - 21) * 256 * 512;
    const int nl = threadIdx.x & 63, iq = threadIdx.x >> 6;
#pragma unroll
    for (int r = 0; r < 16; ++r) {
        int il = iq * 16 + r;
        ts[il][nl] = w[(size_t)(i0 + il) * 512 + n0 + nl];
    }
    __syncthreads();
    int pb;
    if (n0 < 256) pb = (n0 >> 6) * 128;
    else { int c0 = n0 - 256; pb = (c0 >> 6) * 128 + 64; }
    const int il2 = threadIdx.x & 63, pq = threadIdx.x >> 6;
#pragma unroll
    for (int r = 0; r < 16; ++r) {
        int nl2 = pq * 16 + r;
        float v = ts[il2][nl2];
        size_t dst = ((size_t)kk * 512 + pb + nl2) * 256 + i0 + il2;
        __nv_bfloat16 h = __float2bfloat16(v);
        g_wh[dst] = h;
        g_wl[dst] = __float2bfloat16(v - __bfloat162float(h));
    }
}

// ---------------- embedding gather (fp32 + bf16 hi/lo) ----------------
__global__ void embed_kernel(const int* __restrict__ aw, const int* __restrict__ tw,
                             const float* __restrict__ emb)
{
    int row = blockIdx.x;
    int t   = threadIdx.x;        // 64 threads x float4
    const float4* src; float4* dst; __nv_bfloat16 *h, *l;
    if (row < NB*LA) {
        src = (const float4*)(emb + (size_t)aw[row] * DD);
        size_t e = (size_t)row * DD;
        dst = (float4*)(g_fA[0] + e); h = g_hA[0] + e; l = g_lA[0] + e;
    } else {
        int r = row - NB*LA;
        src = (const float4*)(emb + (size_t)tw[r] * DD);
        size_t e = (size_t)r * DD;
        dst = (float4*)(g_fT[0] + e); h = g_hT[0] + e; l = g_lT[0] + e;
    }
    float4 v = src[t]; dst[t] = v;
    float vs[4] = {v.x, v.y, v.z, v.w};
    int i0 = t * 4;
#pragma unroll
    for (int qq = 0; qq < 4; qq++) {
        __nv_bfloat16 hh = __float2bfloat16(vs[qq]);
        h[i0+qq] = hh;
        l[i0+qq] = __float2bfloat16(vs[qq] - __bfloat162float(hh));
    }
}

// ---------------- mma.sync conv + GLU + residual ----------------
// CTA: 128 positions x 128 (permuted) out-cols. 256 thr = 8 warps (4 M x 2 N).
// 24 K-stages of 32 features, 3-stage cp.async ring, ONE barrier per stage.
// Tiles: 128 rows x 64B, XOR swizzle: chunk' = chunk ^ ((row>>1)&3).
// 3-pass bf16 hi/lo split, PASS-MAJOR mma order (RAW distance 16).
#define STG3    32768u
#define OFF_AL  8192u
#define OFF_BH  16384u
#define OFF_BL  24576u
#define CONV_SMEM (3u*STG3)

__global__ __launch_bounds__(256, 2)
void conv_mma(int layer, int par, int dil, const float* __restrict__ bias)
{
    extern __shared__ char smem[];
    const uint32_t sb = smem_u32(smem);
    const int tid = threadIdx.x;

    int id = blockIdx.x;
    const int q = id & 3;
    int tile = id >> 2;
    int seq, b, l0, L;
    if (tile < 128) { seq = 0; b = tile >> 3; l0 = (tile & 7) << 7; L = LA; }
    else { tile -= 128; seq = 1; b = tile >> 2; l0 = (tile & 3) << 7; L = LT; }

    const float* xin; float* xout;
    const __nv_bfloat16 *xh, *xl; __nv_bfloat16 *oh, *ol;
    if (seq == 0) {
        xin = g_fA[par]; xout = g_fA[1-par];
        xh = g_hA[par]; xl = g_lA[par]; oh = g_hA[1-par]; ol = g_lA[1-par];
    } else {
        xin = g_fT[par]; xout = g_fT[1-par];
        xh = g_hT[par]; xl = g_lT[par]; oh = g_hT[1-par]; ol = g_lT[1-par];
    }

    const size_t wbase = (size_t)layer * 3 * 512 * 256;
    const int r0i = tid >> 2;       // cp.async row base (2 rows/thread: +0, +64)
    const int ci  = tid & 3;        // 16B chunk within 64B row

#define ISSUE(sn, bufo_) do {                                                   \
        int k_ = (sn) >> 3, j0_ = ((sn) & 7) << 5;                              \
        int lb_ = l0 + (k_ - 1) * dil;                                          \
        _Pragma("unroll")                                                       \
        for (int i_ = 0; i_ < 2; ++i_) {                                        \
            int r_ = r0i + (i_ << 6);                                           \
            int l_ = lb_ + r_;                                                  \
            uint32_t dA_ = (bufo_) + (uint32_t)(r_ * 64                         \
                           + ((ci ^ ((r_ >> 1) & 3)) << 4));                    \
            uint32_t ok_ = (l_ >= 0 && l_ < L) ? 16u : 0u;                      \
            size_t ea_ = ((size_t)b * L + (ok_ ? l_ : 0)) * 256 + j0_ + (ci<<3);\
            cpa16(dA_,          xh + ea_, ok_);                                 \
            cpa16(dA_ + OFF_AL, xl + ea_, ok_);                                 \
            size_t eb_ = wbase + ((size_t)(k_ * 512 + q * 128 + r_)) * 256      \
                         + j0_ + (ci << 3);                                     \
            cpa16(dA_ + OFF_BH, g_wh + eb_, 16u);                               \
            cpa16(dA_ + OFF_BL, g_wl + eb_, 16u);                               \
        }                                                                       \
        cpa_commit();                                                           \
    } while (0)

    float acc[2][8][4];
#pragma unroll
    for (int mt = 0; mt < 2; ++mt)
#pragma unroll
        for (int nt = 0; nt < 8; ++nt)
#pragma unroll
            for (int e = 0; e < 4; ++e) acc[mt][nt][e] = 0.f;

    const int lane = tid & 31, warp = tid >> 5;
    const int mw = warp >> 1, nw = warp & 1;
    uint32_t offA[2], offB[4];
    {
        const int cA0 = lane >> 4;
#pragma unroll
        for (int mt = 0; mt < 2; ++mt) {
            int r = mw*32 + mt*16 + (lane & 15);
            offA[mt] = (uint32_t)(r * 64 + ((cA0 ^ ((r >> 1) & 3)) << 4));
        }
        const int rBl = (lane & 7) | ((lane >> 4) << 3);
        const int cB0 = (lane >> 3) & 1;
#pragma unroll
        for (int ng = 0; ng < 4; ++ng) {
            int r = nw*64 + ng*16 + rBl;
            offB[ng] = (uint32_t)(r * 64 + ((cB0 ^ ((r >> 1) & 3)) << 4));
        }
    }

    ISSUE(0, sb);
    ISSUE(1, sb + STG3);
    for (int s = 0; s < 24; ++s) {
        if (s < 23) asm volatile("cp.async.wait_group 1;" ::: "memory");
        else        asm volatile("cp.async.wait_group 0;" ::: "memory");
        __syncthreads();
        if (s < 22) {
            uint32_t ibuf = sb + (uint32_t)((s + 2) % 3) * STG3;
            ISSUE(s + 2, ibuf);
        }
        const uint32_t bufo = sb + (uint32_t)(s % 3) * STG3;
#pragma unroll
        for (int ks = 0; ks < 2; ++ks) {
            const uint32_t kx = (uint32_t)(ks << 5);
            uint32_t ah[2][4], al[2][4], bh[4][4], bl[4][4];
#pragma unroll
            for (int mt = 0; mt < 2; ++mt) {
                ldsm4(ah[mt], (bufo +          offA[mt]) ^ kx);
                ldsm4(al[mt], (bufo + OFF_AL + offA[mt]) ^ kx);
            }
#pragma unroll
            for (int ng = 0; ng < 4; ++ng) {
                ldsm4(bh[ng], (bufo + OFF_BH + offB[ng]) ^ kx);
                ldsm4(bl[ng], (bufo + OFF_BL + offB[ng]) ^ kx);
            }
            // pass 1: Ah*Bh
#pragma unroll
            for (int ng = 0; ng < 4; ++ng)
#pragma unroll
                for (int mt = 0; mt < 2; ++mt) {
                    mma16816(acc[mt][2*ng],   ah[mt], bh[ng]);
                    mma16816(acc[mt][2*ng+1], ah[mt], bh[ng] + 2);
                }
            // pass 2: Ah*Bl
#pragma unroll
            for (int ng = 0; ng < 4; ++ng)
#pragma unroll
                for (int mt = 0; mt < 2; ++mt) {
                    mma16816(acc[mt][2*ng],   ah[mt], bl[ng]);
                    mma16816(acc[mt][2*ng+1], ah[mt], bl[ng] + 2);
                }
            // pass 3: Al*Bh
#pragma unroll
            for (int ng = 0; ng < 4; ++ng)
#pragma unroll
                for (int mt = 0; mt < 2; ++mt) {
                    mma16816(acc[mt][2*ng],   al[mt], bh[ng]);
                    mma16816(acc[mt][2*ng+1], al[mt], bh[ng] + 2);
                }
        }
    }
#undef ISSUE
    __syncthreads();

    // ---- epilogue: dump accums to smem, then fused bias+GLU+residual ----
    float* Ds = (float*)smem;     // [128][132]
#pragma unroll
    for (int mt = 0; mt < 2; ++mt)
#pragma unroll
        for (int nt = 0; nt < 8; ++nt) {
            int r = mw*32 + mt*16 + (lane >> 2);
            int c = nw*64 + nt*8 + ((lane & 3) << 1);
            *(float2*)&Ds[r * 132 + c]       = make_float2(acc[mt][nt][0], acc[mt][nt][1]);
            *(float2*)&Ds[(r + 8) * 132 + c] = make_float2(acc[mt][nt][2], acc[mt][nt][3]);
        }
    __syncthreads();

    const int n  = tid & 63, pg = tid >> 6;
    const int ch = q * 64 + n;
    const float ba = bias[ch], bg = bias[256 + ch];
#pragma unroll 4
    for (int i = 0; i < 32; ++i) {
        int p = pg + (i << 2);
        float a = Ds[p * 132 + n] + ba;
        float g = Ds[p * 132 + 64 + n] + bg;
        size_t gi = (((size_t)b * L) + l0 + p) * 256 + ch;
        float y = xin[gi] + a / (1.0f + __expf(-g));
        xout[gi] = y;
        __nv_bfloat16 h = __float2bfloat16(y);
        oh[gi] = h;
        ol[gi] = __float2bfloat16(y - __bfloat162float(h));
    }
}

// ---------------- squared norms + rowmax zeroing ----------------
__global__ void norms_kernel()
{
    int gtid = blockIdx.x * blockDim.x + threadIdx.x;
    if (gtid < NB*LA) g_rowmax[gtid] = 0.f;
    int gwarp = gtid >> 5;
    int lane  = threadIdx.x & 31;
    const int total = NB*LA + NB*LT;
    if (gwarp >= total) return;
    const float* row = (gwarp < NB*LA) ? (g_fA[0] + (size_t)gwarp * DD)
                                       : (g_fT[0] + (size_t)(gwarp - NB*LA) * DD);
    const float4* r4 = (const float4*)row;
    float s = 0.f;
#pragma unroll
    for (int i = 0; i < 2; ++i) {
        float4 v = r4[lane + i * 32];
        s += v.x*v.x + v.y*v.y + v.z*v.z + v.w*v.w;
    }
#pragma unroll
    for (int off = 16; off > 0; off >>= 1) s += __shfl_xor_sync(0xffffffffu, s, off);
    if (lane == 0) g_norm[gwarp] = s;
}

// ---------------- tensor-core pairwise distance + row-max ----------------
// CTA: 128 art rows x 128 tpl rows, K=256 in 8 stages of 32, ring-3 cp.async.
// dot via 3-pass bf16 hi/lo mma; epilogue computes exp(-dist)*tm, warp rowmax,
// atomicMax(float-as-int, all values >= 0) into g_rowmax.
#define D_OFF_AL 8192u
#define D_OFF_TH 16384u
#define D_OFF_TL 24576u
#define DIST_SMEM (3u*STG3)

__global__ __launch_bounds__(256, 2)
void distance_mma(const float* __restrict__ tm)
{
    extern __shared__ char smem[];
    const uint32_t sb = smem_u32(smem);
    const int tid = threadIdx.x;
    const int b  = blockIdx.z;
    const int a0 = blockIdx.x * 128;
    const int t0 = blockIdx.y * 128;

    const __nv_bfloat16* Ah = g_hA[0] + ((size_t)b * LA + a0) * DD;
    const __nv_bfloat16* Al = g_lA[0] + ((size_t)b * LA + a0) * DD;
    const __nv_bfloat16* Th = g_hT[0] + ((size_t)b * LT + t0) * DD;
    const __nv_bfloat16* Tl = g_lT[0] + ((size_t)b * LT + t0) * DD;

    const int r0i = tid >> 2;
    const int ci  = tid & 3;

#define DISSUE(sn, bufo_) do {                                                  \
        int j0_ = (sn) << 5;                                                    \
        _Pragma("unroll")                                                       \
        for (int i_ = 0; i_ < 2; ++i_) {                                        \
            int r_ = r0i + (i_ << 6);                                           \
            uint32_t dA_ = (bufo_) + (uint32_t)(r_ * 64                         \
                           + ((ci ^ ((r_ >> 1) & 3)) << 4));                    \
            size_t e_ = (size_t)r_ * 256 + j0_ + (ci << 3);                     \
            cpa16(dA_,            Ah + e_, 16u);                                \
            cpa16(dA_ + D_OFF_AL, Al + e_, 16u);                                \
            cpa16(dA_ + D_OFF_TH, Th + e_, 16u);                                \
            cpa16(dA_ + D_OFF_TL, Tl + e_, 16u);                                \
        }                                                                       \
        cpa_commit();                                                           \
    } while (0)

    float acc[2][8][4];
#pragma unroll
    for (int mt = 0; mt < 2; ++mt)
#pragma unroll
        for (int nt = 0; nt < 8; ++nt)
#pragma unroll
            for (int e = 0; e < 4; ++e) acc[mt][nt][e] = 0.f;

    const int lane = tid & 31, warp = tid >> 5;
    const int mw = warp >> 1, nw = warp & 1;
    uint32_t offA[2], offB[4];
    {
        const int cA0 = lane >> 4;
#pragma unroll
        for (int mt = 0; mt < 2; ++mt) {
            int r = mw*32 + mt*16 + (lane & 15);
            offA[mt] = (uint32_t)(r * 64 + ((cA0 ^ ((r >> 1) & 3)) << 4));
        }
        const int rBl = (lane & 7) | ((lane >> 4) << 3);
        const int cB0 = (lane >> 3) & 1;
#pragma unroll
        for (int ng = 0; ng < 4; ++ng) {
            int r = nw*64 + ng*16 + rBl;
            offB[ng] = (uint32_t)(r * 64 + ((cB0 ^ ((r >> 1) & 3)) << 4));
        }
    }

    DISSUE(0, sb);
    DISSUE(1, sb + STG3);
    for (int s = 0; s < 8; ++s) {
        if (s < 7) asm volatile("cp.async.wait_group 1;" ::: "memory");
        else       asm volatile("cp.async.wait_group 0;" ::: "memory");
        __syncthreads();
        if (s < 6) {
            uint32_t ibuf = sb + (uint32_t)((s + 2) % 3) * STG3;
            DISSUE(s + 2, ibuf);
        }
        const uint32_t bufo = sb + (uint32_t)(s % 3) * STG3;
#pragma unroll
        for (int ks = 0; ks < 2; ++ks) {
            const uint32_t kx = (uint32_t)(ks << 5);
            uint32_t ah[2][4], al[2][4], bh[4][4], bl[4][4];
#pragma unroll
            for (int mt = 0; mt < 2; ++mt) {
                ldsm4(ah[mt], (bufo +            offA[mt]) ^ kx);
                ldsm4(al[mt], (bufo + D_OFF_AL + offA[mt]) ^ kx);
            }
#pragma unroll
            for (int ng = 0; ng < 4; ++ng) {
                ldsm4(bh[ng], (bufo + D_OFF_TH + offB[ng]) ^ kx);
                ldsm4(bl[ng], (bufo + D_OFF_TL + offB[ng]) ^ kx);
            }
#pragma unroll
            for (int ng = 0; ng < 4; ++ng)
#pragma unroll
                for (int mt = 0; mt < 2; ++mt) {
                    mma16816(acc[mt][2*ng],   ah[mt], bh[ng]);
                    mma16816(acc[mt][2*ng+1], ah[mt], bh[ng] + 2);
                }
#pragma unroll
            for (int ng = 0; ng < 4; ++ng)
#pragma unroll
                for (int mt = 0; mt < 2; ++mt) {
                    mma16816(acc[mt][2*ng],   ah[mt], bl[ng]);
                    mma16816(acc[mt][2*ng+1], ah[mt], bl[ng] + 2);
                }
#pragma unroll
            for (int ng = 0; ng < 4; ++ng)
#pragma unroll
                for (int mt = 0; mt < 2; ++mt) {
                    mma16816(acc[mt][2*ng],   al[mt], bh[ng]);
                    mma16816(acc[mt][2*ng+1], al[mt], bh[ng] + 2);
                }
        }
    }
#undef DISSUE

    // ---- epilogue: dist -> exp -> rowmax -> atomicMax ----
    const float* a2  = g_norm + b * LA + a0;
    const float* t2  = g_norm + NB*LA + b * LT + t0;
    const float* tmb = tm + b * LT + t0;

    float t2v[16], tmv[16];
#pragma unroll
    for (int nt = 0; nt < 8; ++nt)
#pragma unroll
        for (int e = 0; e < 2; ++e) {
            int c = nw*64 + nt*8 + ((lane & 3) << 1) + e;
            t2v[nt*2+e] = t2[c];
            tmv[nt*2+e] = tmb[c];
        }

#pragma unroll
    for (int mt = 0; mt < 2; ++mt)
#pragma unroll
        for (int hf = 0; hf < 2; ++hf) {
            int r = mw*32 + mt*16 + (lane >> 2) + hf*8;
            float an = a2[r];
            float m = 0.f;
#pragma unroll
            for (int nt = 0; nt < 8; ++nt)
#pragma unroll
                for (int e = 0; e < 2; ++e) {
                    float d = acc[mt][nt][hf*2 + e];
                    float dist = fmaxf(an + t2v[nt*2+e] - 2.0f * d, 0.0f);
                    float v = __expf(-dist) * tmv[nt*2+e];
                    m = fmaxf(m, v);
                }
            m = fmaxf(m, __shfl_xor_sync(0xffffffffu, m, 1));
            m = fmaxf(m, __shfl_xor_sync(0xffffffffu, m, 2));
            if ((lane & 3) == 0)
                atomicMax((int*)&g_rowmax[b * LA + a0 + r], __float_as_int(m));
        }
}

// ---------------- top-10 + tiny MLP ----------------
__global__ void topk_mlp_kernel(const float* __restrict__ am,
                                const float* __restrict__ ff1w, const float* __restrict__ ff1b,
                                const float* __restrict__ ff2w, const float* __restrict__ ff2b,
                                float* __restrict__ out)
{
    const int b = blockIdx.x;
    __shared__ float vals[1024];
    __shared__ float rv[256];
    __shared__ int   ri[256];
    __shared__ float top[10];
    __shared__ float hbuf[10];
    const int tid = threadIdx.x;

    for (int i = tid; i < 1024; i += 256)
        vals[i] = g_rowmax[b * LA + i] * am[b * LA + i];
    __syncthreads();

    for (int it = 0; it < 10; ++it) {
        float best = -1e30f; int bi = 0;
        for (int i = tid; i < 1024; i += 256) {
            float v = vals[i];
            if (v > best) { best = v; bi = i; }
        }
        rv[tid] = best; ri[tid] = bi;
        __syncthreads();
        for (int s = 128; s > 0; s >>= 1) {
            if (tid < s) {
                float ov = rv[tid + s]; int oi = ri[tid + s];
                if (ov > rv[tid] || (ov == rv[tid] && oi < ri[tid])) { rv[tid] = ov; ri[tid] = oi; }
            }
            __syncthreads();
        }
        if (tid == 0) { top[it] = rv[0]; vals[ri[0]] = -1e30f; }
        __syncthreads();
    }

    if (tid < 10) {
        float h = ff1b[tid];
#pragma unroll
        for (int i = 0; i < 10; i++) h += top[i] * ff1w[i * 10 + tid];
        hbuf[tid] = fmaxf(h, 0.f);
    }
    __syncthreads();
    if (tid == 0) {
        float o = ff2b[0];
#pragma unroll
        for (int i = 0; i < 10; i++) o += hbuf[i] * ff2w[i];
        out[b] = o;
    }
}

// ---------------- launch ----------------
extern "C" void kernel_launch(void* const* d_in, const int* in_sizes, int n_in,
                              void* d_out, int out_size)
{
    const int*   aw    = (const int*)  d_in[0];
    const int*   tw    = (const int*)  d_in[2];
    const float* am    = (const float*)d_in[4];
    const float* tm    = (const float*)d_in[5];
    const float* emb   = (const float*)d_in[6];
    const float* exp_w = (const float*)d_in[7];
    const float* exp_b = (const float*)d_in[8];
    const float* ref_w = (const float*)d_in[9];
    const float* ref_b = (const float*)d_in[10];
    const float* ff1w  = (const float*)d_in[11];
    const float* ff1b  = (const float*)d_in[12];
    const float* ff2w  = (const float*)d_in[13];
    const float* ff2b  = (const float*)d_in[14];
    float* out = (float*)d_out;

    cudaFuncSetAttribute(conv_mma, cudaFuncAttributeMaxDynamicSharedMemorySize, CONV_SMEM);
    cudaFuncSetAttribute(distance_mma, cudaFuncAttributeMaxDynamicSharedMemorySize, DIST_SMEM);

    wprep_kernel<<<dim3(8, 4, 30), 256>>>(exp_w, ref_w);
    embed_kernel<<<NB*LA + NB*LT, 64>>>(aw, tw, emb);

    const int dils[10] = {1, 2, 4, 8, 16, 32, 32, 1, 1, 1};
    for (int layer = 0; layer < 10; ++layer) {
        const float* bi = (layer < 7) ? exp_b + layer * 512
                                      : ref_b + (layer - 7) * 512;
        conv_mma<<<768, 256, CONV_SMEM>>>(layer, layer & 1, dils[layer], bi);
    }

    norms_kernel<<<(NB*LA + NB*LT) / 8, 256>>>();
    distance_mma<<<dim3(8, 4, NB), 256, DIST_SMEM>>>(tm);
    topk_mlp_kernel<<<NB, 256>>>(am, ff1w, ff1b, ff2w, ff2b, out);
}